// round 7
// baseline (speedup 1.0000x reference)
#include <cuda_runtime.h>
#include <cuda_bf16.h>
#include <cstdint>

typedef __nv_bfloat16 bf16;

#define SEQ 2048
#define HD  128
#define TS  128
#define NKT 16
#define STRIDE 136   // bf16 elements per smem row (128 + 8 pad, conflict-free for ldmatrix)

// smem byte offsets
#define OFF_QH  0
#define OFF_QL  34816
#define OFF_KH  69632
#define OFF_KL  104448
#define OFF_VH  139264
#define OFF_VL  174080
#define OFF_DEN 208896
#define OFF_INV 209408
#define SMEM_TOTAL 209920

__device__ __forceinline__ uint32_t smem_u32(const void* p) {
    return (uint32_t)__cvta_generic_to_shared(p);
}

__device__ __forceinline__ void ldsm_x4(uint32_t& r0, uint32_t& r1, uint32_t& r2, uint32_t& r3, uint32_t addr) {
    asm volatile("ldmatrix.sync.aligned.m8n8.x4.shared.b16 {%0,%1,%2,%3}, [%4];"
                 : "=r"(r0), "=r"(r1), "=r"(r2), "=r"(r3) : "r"(addr));
}
__device__ __forceinline__ void ldsm_x4_t(uint32_t& r0, uint32_t& r1, uint32_t& r2, uint32_t& r3, uint32_t addr) {
    asm volatile("ldmatrix.sync.aligned.m8n8.x4.trans.shared.b16 {%0,%1,%2,%3}, [%4];"
                 : "=r"(r0), "=r"(r1), "=r"(r2), "=r"(r3) : "r"(addr));
}
__device__ __forceinline__ void mma_bf16(float* d, const uint32_t* a, uint32_t b0, uint32_t b1) {
    asm volatile("mma.sync.aligned.m16n8k16.row.col.f32.bf16.bf16.f32 "
                 "{%0,%1,%2,%3}, {%4,%5,%6,%7}, {%8,%9}, {%0,%1,%2,%3};"
                 : "+f"(d[0]), "+f"(d[1]), "+f"(d[2]), "+f"(d[3])
                 : "r"(a[0]), "r"(a[1]), "r"(a[2]), "r"(a[3]), "r"(b0), "r"(b1));
}

// Streaming (evict-first) 64-bit store: outputs are write-once, never re-read by this kernel.
__device__ __forceinline__ void stg_cs_f2(float* p, float x, float y) {
    asm volatile("st.global.cs.v2.f32 [%0], {%1, %2};" :: "l"(p), "f"(x), "f"(y) : "memory");
}

__device__ __forceinline__ uint32_t pack_bf16(float x, float y) {
    __nv_bfloat162 t = __floats2bfloat162_rn(x, y);   // low = x, high = y
    return *reinterpret_cast<uint32_t*>(&t);
}

// Split two floats into (hi, lo) bf16 pairs: x = hi + lo to ~2^-18 relative.
__device__ __forceinline__ void split2(float x, float y, uint32_t& hi, uint32_t& lo) {
    float hx = __bfloat162float(__float2bfloat16_rn(x));
    float hy = __bfloat162float(__float2bfloat16_rn(y));
    hi = pack_bf16(hx, hy);
    lo = pack_bf16(x - hx, y - hy);
}

// Load a 128x128 fp32 tile from gmem, scale, split into hi/lo bf16 smem tiles.
__device__ __forceinline__ void load_split(const float* __restrict__ g, bf16* sh, bf16* sl,
                                           int tid, float scale) {
#pragma unroll
    for (int i = 0; i < 16; i++) {
        int idx = tid + (i << 8);          // 0..4095 (float4 index)
        int r = idx >> 5;
        int c = (idx & 31) << 2;
        float4 f = *reinterpret_cast<const float4*>(g + (size_t)r * HD + c);
        uint32_t h0, l0, h1, l1;
        split2(f.x * scale, f.y * scale, h0, l0);
        split2(f.z * scale, f.w * scale, h1, l1);
        *reinterpret_cast<uint2*>(sh + r * STRIDE + c) = make_uint2(h0, h1);
        *reinterpret_cast<uint2*>(sl + r * STRIDE + c) = make_uint2(l0, l1);
    }
}

// Hi-only variant for pass 1 (denominator needs only the bf16-rounded values).
__device__ __forceinline__ void load_hi(const float* __restrict__ g, bf16* sh, int tid) {
#pragma unroll
    for (int i = 0; i < 16; i++) {
        int idx = tid + (i << 8);
        int r = idx >> 5;
        int c = (idx & 31) << 2;
        float4 f = *reinterpret_cast<const float4*>(g + (size_t)r * HD + c);
        uint32_t h0 = pack_bf16(__bfloat162float(__float2bfloat16_rn(f.x)),
                                __bfloat162float(__float2bfloat16_rn(f.y)));
        uint32_t h1 = pack_bf16(__bfloat162float(__float2bfloat16_rn(f.z)),
                                __bfloat162float(__float2bfloat16_rn(f.w)));
        *reinterpret_cast<uint2*>(sh + r * STRIDE + c) = make_uint2(h0, h1);
    }
}

extern "C" __global__ void __launch_bounds__(256, 1)
sdpa_kernel(const float* __restrict__ gq, const float* __restrict__ gk,
            const float* __restrict__ gv, float* __restrict__ gctx,
            float* __restrict__ gatt)
{
    extern __shared__ char smem[];
    bf16* sQh = (bf16*)(smem + OFF_QH);
    bf16* sQl = (bf16*)(smem + OFF_QL);
    bf16* sKh = (bf16*)(smem + OFF_KH);
    bf16* sKl = (bf16*)(smem + OFF_KL);
    bf16* sVh = (bf16*)(smem + OFF_VH);
    bf16* sVl = (bf16*)(smem + OFF_VL);
    float* sDen = (float*)(smem + OFF_DEN);
    float* sInv = (float*)(smem + OFF_INV);

    const int tid  = threadIdx.x;
    const int lane = tid & 31;
    const int wid  = tid >> 5;
    const int wm   = wid & 3;   // m-group of warp (32 q-rows)
    const int wn   = wid >> 2;  // n-group of warp (64 cols: seq in QK phase, d in PV phase)
    const int b    = blockIdx.y;
    const int qt   = blockIdx.x;

    const int lr = lane & 15;          // ldmatrix row-within-16
    const int lc = (lane >> 4) << 3;   // ldmatrix 8-col chunk

    const float scale = 0.08838834764831845f; // 1/sqrt(128), folded into Q

    const float* qg = gq + (size_t)(b * SEQ + qt * TS) * HD;
    const float* kg = gk + (size_t)b * SEQ * HD;
    const float* vg = gv + (size_t)b * SEQ * HD;

    load_split(qg, sQh, sQl, tid, scale);
    if (tid < 128) sDen[tid] = 0.0f;

    // Loop-invariant ldmatrix base addresses for this thread's Q fragments.
    uint32_t qh_addr[2][8], ql_addr[2][8];
#pragma unroll
    for (int mi = 0; mi < 2; mi++)
#pragma unroll
        for (int ks = 0; ks < 8; ks++) {
            int off = (wm * 32 + mi * 16 + lr) * STRIDE + ks * 16 + lc;
            qh_addr[mi][ks] = smem_u32(sQh + off);
            ql_addr[mi][ks] = smem_u32(sQl + off);
        }

    // ---------------- PASS 1: row denominators (hi-only bf16 QK^T) ----------------
    // Double-buffered K-hi: ping-pong between sKh and sVh (V buffers idle in pass 1).
    float den[2][2] = {{0.f, 0.f}, {0.f, 0.f}};
    bf16* kbuf[2] = { sKh, sVh };

    load_hi(kg, kbuf[0], tid);
    __syncthreads();

    // Q-hi fragments are loop-invariant across all K tiles: hoist into registers.
    uint32_t qa[2][8][4];
#pragma unroll
    for (int mi = 0; mi < 2; mi++)
#pragma unroll
        for (int ks = 0; ks < 8; ks++)
            ldsm_x4(qa[mi][ks][0], qa[mi][ks][1], qa[mi][ks][2], qa[mi][ks][3],
                    qh_addr[mi][ks]);

#pragma unroll 1
    for (int kt = 0; kt < NKT; kt++) {
        // Prefetch next K tile into the other buffer (LDGs issue before compute).
        if (kt + 1 < NKT)
            load_hi(kg + (size_t)(kt + 1) * TS * HD, kbuf[(kt + 1) & 1], tid);

        bf16* sK = kbuf[kt & 1];
        float acc[2][8][4];
#pragma unroll
        for (int mi = 0; mi < 2; mi++)
#pragma unroll
            for (int nf = 0; nf < 8; nf++)
#pragma unroll
                for (int e = 0; e < 4; e++) acc[mi][nf][e] = 0.f;

#pragma unroll
        for (int ks = 0; ks < 8; ks++) {
            uint32_t kb[4][4];
#pragma unroll
            for (int nj = 0; nj < 4; nj++)
                ldsm_x4(kb[nj][0], kb[nj][1], kb[nj][2], kb[nj][3],
                        smem_u32(sK + (wn * 64 + nj * 16 + lr) * STRIDE + ks * 16 + lc));
#pragma unroll
            for (int mi = 0; mi < 2; mi++)
#pragma unroll
                for (int nj = 0; nj < 4; nj++) {
                    mma_bf16(acc[mi][2 * nj],     qa[mi][ks], kb[nj][0], kb[nj][2]);
                    mma_bf16(acc[mi][2 * nj + 1], qa[mi][ks], kb[nj][1], kb[nj][3]);
                }
        }
#pragma unroll
        for (int mi = 0; mi < 2; mi++)
#pragma unroll
            for (int nf = 0; nf < 8; nf++) {
                den[mi][0] += __expf(acc[mi][nf][0]) + __expf(acc[mi][nf][1]);
                den[mi][1] += __expf(acc[mi][nf][2]) + __expf(acc[mi][nf][3]);
            }
        __syncthreads();   // next-tile stores visible; current reads done before overwrite
    }

    // Hoisted pass-2 tile-0 load: buffers are dead after the loop-end barrier, and the
    // reduction below only touches registers + sDen/sInv. The barriers inside the
    // reduction make these stores visible before pass 2 reads them.
    load_split(kg, sKh, sKl, tid, 1.0f);
    load_split(vg, sVh, sVl, tid, 1.0f);

    // reduce denominator: 4 lanes of a row-quad, then across the two wn warps via smem atomics
#pragma unroll
    for (int mi = 0; mi < 2; mi++)
#pragma unroll
        for (int h = 0; h < 2; h++) {
            den[mi][h] += __shfl_xor_sync(0xffffffffu, den[mi][h], 1);
            den[mi][h] += __shfl_xor_sync(0xffffffffu, den[mi][h], 2);
        }
    if ((lane & 3) == 0) {
#pragma unroll
        for (int mi = 0; mi < 2; mi++)
#pragma unroll
            for (int h = 0; h < 2; h++)
                atomicAdd(&sDen[wm * 32 + mi * 16 + h * 8 + (lane >> 2)], den[mi][h]);
    }
    __syncthreads();
    if (tid < 128) sInv[tid] = 1.0f / sDen[tid];
    __syncthreads();

    float inv[2][2];
#pragma unroll
    for (int mi = 0; mi < 2; mi++)
#pragma unroll
        for (int h = 0; h < 2; h++)
            inv[mi][h] = sInv[wm * 32 + mi * 16 + h * 8 + (lane >> 2)];

    // ---------------- PASS 2: precise scores, attention write, P@V ----------------
    float ctx[2][8][4];
#pragma unroll
    for (int mi = 0; mi < 2; mi++)
#pragma unroll
        for (int nf = 0; nf < 8; nf++)
#pragma unroll
            for (int e = 0; e < 4; e++) ctx[mi][nf][e] = 0.f;

#pragma unroll 1
    for (int kt = 0; kt < NKT; kt++) {
        if (kt > 0) {   // tile 0 was hoisted above the reduction
            load_split(kg + (size_t)kt * TS * HD, sKh, sKl, tid, 1.0f);
            load_split(vg + (size_t)kt * TS * HD, sVh, sVl, tid, 1.0f);
        }
        __syncthreads();

        // S = (Qh+Ql)(Kh+Kl)^T  (3 mma combos; Ql*Kl dropped, ~2^-18)
        float acc[2][8][4];
#pragma unroll
        for (int mi = 0; mi < 2; mi++)
#pragma unroll
            for (int nf = 0; nf < 8; nf++)
#pragma unroll
                for (int e = 0; e < 4; e++) acc[mi][nf][e] = 0.f;

#pragma unroll
        for (int ks = 0; ks < 8; ks++) {
            uint32_t qh[2][4], qlo[2][4], kh[4][4], klo[4][4];
#pragma unroll
            for (int mi = 0; mi < 2; mi++) {
                ldsm_x4(qh[mi][0], qh[mi][1], qh[mi][2], qh[mi][3], qh_addr[mi][ks]);
                ldsm_x4(qlo[mi][0], qlo[mi][1], qlo[mi][2], qlo[mi][3], ql_addr[mi][ks]);
            }
#pragma unroll
            for (int nj = 0; nj < 4; nj++) {
                int off = (wn * 64 + nj * 16 + lr) * STRIDE + ks * 16 + lc;
                ldsm_x4(kh[nj][0], kh[nj][1], kh[nj][2], kh[nj][3], smem_u32(sKh + off));
                ldsm_x4(klo[nj][0], klo[nj][1], klo[nj][2], klo[nj][3], smem_u32(sKl + off));
            }
#pragma unroll
            for (int mi = 0; mi < 2; mi++)
#pragma unroll
                for (int nj = 0; nj < 4; nj++) {
                    mma_bf16(acc[mi][2 * nj],     qh[mi],  kh[nj][0],  kh[nj][2]);
                    mma_bf16(acc[mi][2 * nj],     qh[mi],  klo[nj][0], klo[nj][2]);
                    mma_bf16(acc[mi][2 * nj],     qlo[mi], kh[nj][0],  kh[nj][2]);
                    mma_bf16(acc[mi][2 * nj + 1], qh[mi],  kh[nj][1],  kh[nj][3]);
                    mma_bf16(acc[mi][2 * nj + 1], qh[mi],  klo[nj][1], klo[nj][3]);
                    mma_bf16(acc[mi][2 * nj + 1], qlo[mi], kh[nj][1],  kh[nj][3]);
                }
        }
        __syncthreads();   // everyone done reading K smem before it becomes P storage

        // P = exp(S) * inv_denom: write fp32 attention to gmem (streaming), split P into sKh/sKl
        float* attb = gatt + ((size_t)(b * SEQ + qt * TS)) * SEQ + (size_t)kt * TS;
#pragma unroll
        for (int mi = 0; mi < 2; mi++) {
            int r0 = wm * 32 + mi * 16 + (lane >> 2);
            int r1 = r0 + 8;
#pragma unroll
            for (int nf = 0; nf < 8; nf++) {
                int col = wn * 64 + nf * 8 + 2 * (lane & 3);
                float p00 = __expf(acc[mi][nf][0]) * inv[mi][0];
                float p01 = __expf(acc[mi][nf][1]) * inv[mi][0];
                float p10 = __expf(acc[mi][nf][2]) * inv[mi][1];
                float p11 = __expf(acc[mi][nf][3]) * inv[mi][1];
                stg_cs_f2(attb + (size_t)r0 * SEQ + col, p00, p01);
                stg_cs_f2(attb + (size_t)r1 * SEQ + col, p10, p11);
                uint32_t h, l;
                split2(p00, p01, h, l);
                *reinterpret_cast<uint32_t*>(sKh + r0 * STRIDE + col) = h;
                *reinterpret_cast<uint32_t*>(sKl + r0 * STRIDE + col) = l;
                split2(p10, p11, h, l);
                *reinterpret_cast<uint32_t*>(sKh + r1 * STRIDE + col) = h;
                *reinterpret_cast<uint32_t*>(sKl + r1 * STRIDE + col) = l;
            }
        }
        __syncthreads();

        // ctx += (Ph+Pl)(Vh+Vl)  (3 combos; Pl*Vl dropped)
#pragma unroll
        for (int ks = 0; ks < 8; ks++) {
            uint32_t ph[2][4], pl[2][4], vh[4][4], vl[4][4];
#pragma unroll
            for (int mi = 0; mi < 2; mi++) {
                int off = (wm * 32 + mi * 16 + lr) * STRIDE + ks * 16 + lc;
                ldsm_x4(ph[mi][0], ph[mi][1], ph[mi][2], ph[mi][3], smem_u32(sKh + off));
                ldsm_x4(pl[mi][0], pl[mi][1], pl[mi][2], pl[mi][3], smem_u32(sKl + off));
            }
#pragma unroll
            for (int c = 0; c < 4; c++) {
                int off = (ks * 16 + lr) * STRIDE + wn * 64 + c * 16 + lc;
                ldsm_x4_t(vh[c][0], vh[c][1], vh[c][2], vh[c][3], smem_u32(sVh + off));
                ldsm_x4_t(vl[c][0], vl[c][1], vl[c][2], vl[c][3], smem_u32(sVl + off));
            }
#pragma unroll
            for (int mi = 0; mi < 2; mi++)
#pragma unroll
                for (int c = 0; c < 4; c++) {
                    mma_bf16(ctx[mi][2 * c],     ph[mi], vh[c][0], vh[c][1]);
                    mma_bf16(ctx[mi][2 * c],     ph[mi], vl[c][0], vl[c][1]);
                    mma_bf16(ctx[mi][2 * c],     pl[mi], vh[c][0], vh[c][1]);
                    mma_bf16(ctx[mi][2 * c + 1], ph[mi], vh[c][2], vh[c][3]);
                    mma_bf16(ctx[mi][2 * c + 1], ph[mi], vl[c][2], vl[c][3]);
                    mma_bf16(ctx[mi][2 * c + 1], pl[mi], vh[c][2], vh[c][3]);
                }
        }
        __syncthreads();   // before next kt overwrites K(P)/V smem
    }

    // ---------------- epilogue: write context (streaming) ----------------
    float* cb = gctx + ((size_t)(b * SEQ + qt * TS)) * HD;
#pragma unroll
    for (int mi = 0; mi < 2; mi++) {
        int r0 = wm * 32 + mi * 16 + (lane >> 2);
        int r1 = r0 + 8;
#pragma unroll
        for (int nf = 0; nf < 8; nf++) {
            int col = wn * 64 + nf * 8 + 2 * (lane & 3);
            stg_cs_f2(cb + (size_t)r0 * HD + col, ctx[mi][nf][0], ctx[mi][nf][1]);
            stg_cs_f2(cb + (size_t)r1 * HD + col, ctx[mi][nf][2], ctx[mi][nf][3]);
        }
    }
}

extern "C" void kernel_launch(void* const* d_in, const int* in_sizes, int n_in,
                              void* d_out, int out_size) {
    (void)in_sizes; (void)n_in; (void)out_size;
    const float* q = (const float*)d_in[0];
    const float* k = (const float*)d_in[1];
    const float* v = (const float*)d_in[2];
    float* ctx = (float*)d_out;                                   // [16,2048,128]
    float* att = (float*)d_out + (size_t)16 * 2048 * 128;         // [16,2048,2048]

    cudaFuncSetAttribute(sdpa_kernel, cudaFuncAttributeMaxDynamicSharedMemorySize, SMEM_TOTAL);
    dim3 grid(16, 16);   // (q-tile, batch)
    sdpa_kernel<<<grid, 256, SMEM_TOTAL>>>(q, k, v, ctx, att);
}

// round 9
// speedup vs baseline: 1.0242x; 1.0242x over previous
#include <cuda_runtime.h>
#include <cuda_bf16.h>
#include <cstdint>

typedef __nv_bfloat16 bf16;

#define SEQ 2048
#define HD  128
#define TS  128
#define NKT 16
#define NT  512      // threads per CTA (16 warps, 4x4 warp grid)
#define STRIDE 136   // bf16 elements per smem row (128 + 8 pad, conflict-free for ldmatrix)

// smem byte offsets
#define OFF_QH  0
#define OFF_QL  34816
#define OFF_KH  69632
#define OFF_KL  104448
#define OFF_VH  139264
#define OFF_VL  174080
#define OFF_DEN 208896
#define OFF_INV 209408
#define SMEM_TOTAL 209920

__device__ __forceinline__ uint32_t smem_u32(const void* p) {
    return (uint32_t)__cvta_generic_to_shared(p);
}

__device__ __forceinline__ void ldsm_x4(uint32_t& r0, uint32_t& r1, uint32_t& r2, uint32_t& r3, uint32_t addr) {
    asm volatile("ldmatrix.sync.aligned.m8n8.x4.shared.b16 {%0,%1,%2,%3}, [%4];"
                 : "=r"(r0), "=r"(r1), "=r"(r2), "=r"(r3) : "r"(addr));
}
__device__ __forceinline__ void ldsm_x4_t(uint32_t& r0, uint32_t& r1, uint32_t& r2, uint32_t& r3, uint32_t addr) {
    asm volatile("ldmatrix.sync.aligned.m8n8.x4.trans.shared.b16 {%0,%1,%2,%3}, [%4];"
                 : "=r"(r0), "=r"(r1), "=r"(r2), "=r"(r3) : "r"(addr));
}
__device__ __forceinline__ void mma_bf16(float* d, const uint32_t* a, uint32_t b0, uint32_t b1) {
    asm volatile("mma.sync.aligned.m16n8k16.row.col.f32.bf16.bf16.f32 "
                 "{%0,%1,%2,%3}, {%4,%5,%6,%7}, {%8,%9}, {%0,%1,%2,%3};"
                 : "+f"(d[0]), "+f"(d[1]), "+f"(d[2]), "+f"(d[3])
                 : "r"(a[0]), "r"(a[1]), "r"(a[2]), "r"(a[3]), "r"(b0), "r"(b1));
}

// Streaming (evict-first) 64-bit store: outputs are write-once, never re-read by this kernel.
__device__ __forceinline__ void stg_cs_f2(float* p, float x, float y) {
    asm volatile("st.global.cs.v2.f32 [%0], {%1, %2};" :: "l"(p), "f"(x), "f"(y) : "memory");
}

__device__ __forceinline__ uint32_t pack_bf16(float x, float y) {
    __nv_bfloat162 t = __floats2bfloat162_rn(x, y);   // low = x, high = y
    return *reinterpret_cast<uint32_t*>(&t);
}

// Split two floats into (hi, lo) bf16 pairs: x = hi + lo to ~2^-18 relative.
__device__ __forceinline__ void split2(float x, float y, uint32_t& hi, uint32_t& lo) {
    float hx = __bfloat162float(__float2bfloat16_rn(x));
    float hy = __bfloat162float(__float2bfloat16_rn(y));
    hi = pack_bf16(hx, hy);
    lo = pack_bf16(x - hx, y - hy);
}

// Load a 128x128 fp32 tile from gmem, scale, split into hi/lo bf16 smem tiles.
__device__ __forceinline__ void load_split(const float* __restrict__ g, bf16* sh, bf16* sl,
                                           int tid, float scale) {
#pragma unroll
    for (int i = 0; i < 8; i++) {
        int idx = tid + (i << 9);          // 0..4095 (float4 index)
        int r = idx >> 5;
        int c = (idx & 31) << 2;
        float4 f = *reinterpret_cast<const float4*>(g + (size_t)r * HD + c);
        uint32_t h0, l0, h1, l1;
        split2(f.x * scale, f.y * scale, h0, l0);
        split2(f.z * scale, f.w * scale, h1, l1);
        *reinterpret_cast<uint2*>(sh + r * STRIDE + c) = make_uint2(h0, h1);
        *reinterpret_cast<uint2*>(sl + r * STRIDE + c) = make_uint2(l0, l1);
    }
}

// Hi-only variant for pass 1 (denominator needs only the bf16-rounded values).
__device__ __forceinline__ void load_hi(const float* __restrict__ g, bf16* sh, int tid) {
#pragma unroll
    for (int i = 0; i < 8; i++) {
        int idx = tid + (i << 9);
        int r = idx >> 5;
        int c = (idx & 31) << 2;
        float4 f = *reinterpret_cast<const float4*>(g + (size_t)r * HD + c);
        uint32_t h0 = pack_bf16(__bfloat162float(__float2bfloat16_rn(f.x)),
                                __bfloat162float(__float2bfloat16_rn(f.y)));
        uint32_t h1 = pack_bf16(__bfloat162float(__float2bfloat16_rn(f.z)),
                                __bfloat162float(__float2bfloat16_rn(f.w)));
        *reinterpret_cast<uint2*>(sh + r * STRIDE + c) = make_uint2(h0, h1);
    }
}

extern "C" __global__ void __launch_bounds__(NT, 1)
sdpa_kernel(const float* __restrict__ gq, const float* __restrict__ gk,
            const float* __restrict__ gv, float* __restrict__ gctx,
            float* __restrict__ gatt)
{
    extern __shared__ char smem[];
    bf16* sQh = (bf16*)(smem + OFF_QH);
    bf16* sQl = (bf16*)(smem + OFF_QL);
    bf16* sKh = (bf16*)(smem + OFF_KH);
    bf16* sKl = (bf16*)(smem + OFF_KL);
    bf16* sVh = (bf16*)(smem + OFF_VH);
    bf16* sVl = (bf16*)(smem + OFF_VL);
    float* sDen = (float*)(smem + OFF_DEN);
    float* sInv = (float*)(smem + OFF_INV);

    const int tid  = threadIdx.x;
    const int lane = tid & 31;
    const int wid  = tid >> 5;
    const int wm   = wid & 3;   // m-group of warp (32 q-rows)
    const int wn   = wid >> 2;  // n-group of warp (32 cols: seq in QK phase, d in PV phase)
    const int b    = blockIdx.y;
    const int qt   = blockIdx.x;

    const int lr = lane & 15;          // ldmatrix row-within-16
    const int lc = (lane >> 4) << 3;   // ldmatrix 8-col chunk

    const float scale = 0.08838834764831845f; // 1/sqrt(128), folded into Q

    const float* qg = gq + (size_t)(b * SEQ + qt * TS) * HD;
    const float* kg = gk + (size_t)b * SEQ * HD;
    const float* vg = gv + (size_t)b * SEQ * HD;

    load_split(qg, sQh, sQl, tid, scale);
    if (tid < 128) sDen[tid] = 0.0f;

    // ---------------- PASS 1: row denominators (hi-only bf16 QK^T) ----------------
    // Double-buffered K-hi: ping-pong between sKh and sVh (V buffers idle in pass 1).
    float den[2][2] = {{0.f, 0.f}, {0.f, 0.f}};
    bf16* kbuf[2] = { sKh, sVh };

    load_hi(kg, kbuf[0], tid);
    __syncthreads();

#pragma unroll 1
    for (int kt = 0; kt < NKT; kt++) {
        // Prefetch next K tile into the other buffer (LDGs issue before compute).
        if (kt + 1 < NKT)
            load_hi(kg + (size_t)(kt + 1) * TS * HD, kbuf[(kt + 1) & 1], tid);

        bf16* sK = kbuf[kt & 1];
        float acc[2][4][4];
#pragma unroll
        for (int mi = 0; mi < 2; mi++)
#pragma unroll
            for (int nf = 0; nf < 4; nf++)
#pragma unroll
                for (int e = 0; e < 4; e++) acc[mi][nf][e] = 0.f;

#pragma unroll
        for (int ks = 0; ks < 8; ks++) {
            uint32_t qa[2][4], kb[2][4];
#pragma unroll
            for (int mi = 0; mi < 2; mi++)
                ldsm_x4(qa[mi][0], qa[mi][1], qa[mi][2], qa[mi][3],
                        smem_u32(sQh + (wm * 32 + mi * 16 + lr) * STRIDE + ks * 16 + lc));
#pragma unroll
            for (int nj = 0; nj < 2; nj++)
                ldsm_x4(kb[nj][0], kb[nj][1], kb[nj][2], kb[nj][3],
                        smem_u32(sK + (wn * 32 + nj * 16 + lr) * STRIDE + ks * 16 + lc));
#pragma unroll
            for (int mi = 0; mi < 2; mi++)
#pragma unroll
                for (int nj = 0; nj < 2; nj++) {
                    mma_bf16(acc[mi][2 * nj],     qa[mi], kb[nj][0], kb[nj][2]);
                    mma_bf16(acc[mi][2 * nj + 1], qa[mi], kb[nj][1], kb[nj][3]);
                }
        }
#pragma unroll
        for (int mi = 0; mi < 2; mi++)
#pragma unroll
            for (int nf = 0; nf < 4; nf++) {
                den[mi][0] += __expf(acc[mi][nf][0]) + __expf(acc[mi][nf][1]);
                den[mi][1] += __expf(acc[mi][nf][2]) + __expf(acc[mi][nf][3]);
            }
        __syncthreads();   // next-tile stores visible; current reads done before overwrite
    }

    // Hoisted pass-2 tile-0 load: buffers are dead after the loop-end barrier, and the
    // reduction below only touches registers + sDen/sInv. The barriers inside the
    // reduction make these stores visible before pass 2 reads them.
    load_split(kg, sKh, sKl, tid, 1.0f);
    load_split(vg, sVh, sVl, tid, 1.0f);

    // reduce denominator: 4 lanes of a row-quad, then across the four wn warps via smem atomics
#pragma unroll
    for (int mi = 0; mi < 2; mi++)
#pragma unroll
        for (int h = 0; h < 2; h++) {
            den[mi][h] += __shfl_xor_sync(0xffffffffu, den[mi][h], 1);
            den[mi][h] += __shfl_xor_sync(0xffffffffu, den[mi][h], 2);
        }
    if ((lane & 3) == 0) {
#pragma unroll
        for (int mi = 0; mi < 2; mi++)
#pragma unroll
            for (int h = 0; h < 2; h++)
                atomicAdd(&sDen[wm * 32 + mi * 16 + h * 8 + (lane >> 2)], den[mi][h]);
    }
    __syncthreads();
    if (tid < 128) sInv[tid] = 1.0f / sDen[tid];
    __syncthreads();

    float inv[2][2];
#pragma unroll
    for (int mi = 0; mi < 2; mi++)
#pragma unroll
        for (int h = 0; h < 2; h++)
            inv[mi][h] = sInv[wm * 32 + mi * 16 + h * 8 + (lane >> 2)];

    // ---------------- PASS 2: precise scores, attention write, P@V ----------------
    float ctx[2][2][4];
#pragma unroll
    for (int mi = 0; mi < 2; mi++)
#pragma unroll
        for (int nf = 0; nf < 2; nf++)
#pragma unroll
            for (int e = 0; e < 4; e++) { ctx[mi][nf][e] = 0.f; }
    float ctx2[2][2][4];
#pragma unroll
    for (int mi = 0; mi < 2; mi++)
#pragma unroll
        for (int nf = 0; nf < 2; nf++)
#pragma unroll
            for (int e = 0; e < 4; e++) { ctx2[mi][nf][e] = 0.f; }

#pragma unroll 1
    for (int kt = 0; kt < NKT; kt++) {
        if (kt > 0) {   // tile 0 was hoisted above the reduction
            load_split(kg + (size_t)kt * TS * HD, sKh, sKl, tid, 1.0f);
            load_split(vg + (size_t)kt * TS * HD, sVh, sVl, tid, 1.0f);
        }
        __syncthreads();

        // S = (Qh+Ql)(Kh+Kl)^T  (3 mma combos; Ql*Kl dropped, ~2^-18)
        float acc[2][4][4];
#pragma unroll
        for (int mi = 0; mi < 2; mi++)
#pragma unroll
            for (int nf = 0; nf < 4; nf++)
#pragma unroll
                for (int e = 0; e < 4; e++) acc[mi][nf][e] = 0.f;

#pragma unroll
        for (int ks = 0; ks < 8; ks++) {
            uint32_t qh[2][4], qlo[2][4], kh[2][4], klo[2][4];
#pragma unroll
            for (int mi = 0; mi < 2; mi++) {
                int off = (wm * 32 + mi * 16 + lr) * STRIDE + ks * 16 + lc;
                ldsm_x4(qh[mi][0], qh[mi][1], qh[mi][2], qh[mi][3], smem_u32(sQh + off));
                ldsm_x4(qlo[mi][0], qlo[mi][1], qlo[mi][2], qlo[mi][3], smem_u32(sQl + off));
            }
#pragma unroll
            for (int nj = 0; nj < 2; nj++) {
                int off = (wn * 32 + nj * 16 + lr) * STRIDE + ks * 16 + lc;
                ldsm_x4(kh[nj][0], kh[nj][1], kh[nj][2], kh[nj][3], smem_u32(sKh + off));
                ldsm_x4(klo[nj][0], klo[nj][1], klo[nj][2], klo[nj][3], smem_u32(sKl + off));
            }
#pragma unroll
            for (int mi = 0; mi < 2; mi++)
#pragma unroll
                for (int nj = 0; nj < 2; nj++) {
                    mma_bf16(acc[mi][2 * nj],     qh[mi],  kh[nj][0],  kh[nj][2]);
                    mma_bf16(acc[mi][2 * nj],     qh[mi],  klo[nj][0], klo[nj][2]);
                    mma_bf16(acc[mi][2 * nj],     qlo[mi], kh[nj][0],  kh[nj][2]);
                    mma_bf16(acc[mi][2 * nj + 1], qh[mi],  kh[nj][1],  kh[nj][3]);
                    mma_bf16(acc[mi][2 * nj + 1], qh[mi],  klo[nj][1], klo[nj][3]);
                    mma_bf16(acc[mi][2 * nj + 1], qlo[mi], kh[nj][1],  kh[nj][3]);
                }
        }
        __syncthreads();   // everyone done reading K smem before it becomes P storage

        // P = exp(S) * inv_denom: write fp32 attention to gmem (streaming), split P into sKh/sKl
        float* attb = gatt + ((size_t)(b * SEQ + qt * TS)) * SEQ + (size_t)kt * TS;
#pragma unroll
        for (int mi = 0; mi < 2; mi++) {
            int r0 = wm * 32 + mi * 16 + (lane >> 2);
            int r1 = r0 + 8;
#pragma unroll
            for (int nf = 0; nf < 4; nf++) {
                int col = wn * 32 + nf * 8 + 2 * (lane & 3);
                float p00 = __expf(acc[mi][nf][0]) * inv[mi][0];
                float p01 = __expf(acc[mi][nf][1]) * inv[mi][0];
                float p10 = __expf(acc[mi][nf][2]) * inv[mi][1];
                float p11 = __expf(acc[mi][nf][3]) * inv[mi][1];
                stg_cs_f2(attb + (size_t)r0 * SEQ + col, p00, p01);
                stg_cs_f2(attb + (size_t)r1 * SEQ + col, p10, p11);
                uint32_t h, l;
                split2(p00, p01, h, l);
                *reinterpret_cast<uint32_t*>(sKh + r0 * STRIDE + col) = h;
                *reinterpret_cast<uint32_t*>(sKl + r0 * STRIDE + col) = l;
                split2(p10, p11, h, l);
                *reinterpret_cast<uint32_t*>(sKh + r1 * STRIDE + col) = h;
                *reinterpret_cast<uint32_t*>(sKl + r1 * STRIDE + col) = l;
            }
        }
        __syncthreads();

        // ctx += (Ph+Pl)(Vh+Vl)  (3 combos; Pl*Vl dropped)
#pragma unroll
        for (int ks = 0; ks < 8; ks++) {
            uint32_t ph[2][4], pl[2][4], vh[2][4], vl[2][4];
#pragma unroll
            for (int mi = 0; mi < 2; mi++) {
                int off = (wm * 32 + mi * 16 + lr) * STRIDE + ks * 16 + lc;
                ldsm_x4(ph[mi][0], ph[mi][1], ph[mi][2], ph[mi][3], smem_u32(sKh + off));
                ldsm_x4(pl[mi][0], pl[mi][1], pl[mi][2], pl[mi][3], smem_u32(sKl + off));
            }
#pragma unroll
            for (int c = 0; c < 2; c++) {
                int off = (ks * 16 + lr) * STRIDE + wn * 32 + c * 16 + lc;
                ldsm_x4_t(vh[c][0], vh[c][1], vh[c][2], vh[c][3], smem_u32(sVh + off));
                ldsm_x4_t(vl[c][0], vl[c][1], vl[c][2], vl[c][3], smem_u32(sVl + off));
            }
#pragma unroll
            for (int mi = 0; mi < 2; mi++)
#pragma unroll
                for (int c = 0; c < 2; c++) {
                    mma_bf16(ctx[mi][c],  ph[mi], vh[c][0], vh[c][1]);
                    mma_bf16(ctx[mi][c],  ph[mi], vl[c][0], vl[c][1]);
                    mma_bf16(ctx[mi][c],  pl[mi], vh[c][0], vh[c][1]);
                    mma_bf16(ctx2[mi][c], ph[mi], vh[c][2], vh[c][3]);
                    mma_bf16(ctx2[mi][c], ph[mi], vl[c][2], vl[c][3]);
                    mma_bf16(ctx2[mi][c], pl[mi], vh[c][2], vh[c][3]);
                }
        }
        __syncthreads();   // before next kt overwrites K(P)/V smem
    }

    // ---------------- epilogue: write context (streaming) ----------------
    float* cb = gctx + ((size_t)(b * SEQ + qt * TS)) * HD;
#pragma unroll
    for (int mi = 0; mi < 2; mi++) {
        int r0 = wm * 32 + mi * 16 + (lane >> 2);
        int r1 = r0 + 8;
#pragma unroll
        for (int c = 0; c < 2; c++) {
            int col0 = wn * 32 + c * 16 + 2 * (lane & 3);       // ctx  -> 8-col chunk 0
            int col1 = col0 + 8;                                 // ctx2 -> 8-col chunk 1
            stg_cs_f2(cb + (size_t)r0 * HD + col0, ctx[mi][c][0],  ctx[mi][c][1]);
            stg_cs_f2(cb + (size_t)r1 * HD + col0, ctx[mi][c][2],  ctx[mi][c][3]);
            stg_cs_f2(cb + (size_t)r0 * HD + col1, ctx2[mi][c][0], ctx2[mi][c][1]);
            stg_cs_f2(cb + (size_t)r1 * HD + col1, ctx2[mi][c][2], ctx2[mi][c][3]);
        }
    }
}

extern "C" void kernel_launch(void* const* d_in, const int* in_sizes, int n_in,
                              void* d_out, int out_size) {
    (void)in_sizes; (void)n_in; (void)out_size;
    const float* q = (const float*)d_in[0];
    const float* k = (const float*)d_in[1];
    const float* v = (const float*)d_in[2];
    float* ctx = (float*)d_out;                                   // [16,2048,128]
    float* att = (float*)d_out + (size_t)16 * 2048 * 128;         // [16,2048,2048]

    cudaFuncSetAttribute(sdpa_kernel, cudaFuncAttributeMaxDynamicSharedMemorySize, SMEM_TOTAL);
    dim3 grid(16, 16);   // (q-tile, batch)
    sdpa_kernel<<<grid, NT, SMEM_TOTAL>>>(q, k, v, ctx, att);
}